// round 3
// baseline (speedup 1.0000x reference)
#include <cuda_runtime.h>

#define HH 4096
#define WW 1024
#define SS 16
#define NSEG 17
#define NCH 64           // 64-row chunks per column
#define NBH 8            // row-chunk blocks in kernel B (each = 8 warps x 64 rows)
#define WIN 20.0f

// Scratch (__device__ globals; no allocation allowed)
__device__ float  g_p64[NCH * WW];            // per-64-row-chunk column sums
__device__ double g_hA[NBH * NSEG * WW];      // hard-pass sum(x)   partials
__device__ double g_hC[NBH * NSEG * WW];      // hard-pass sum(x^2) partials
__device__ float  g_hB[NBH * NSEG * WW];      // hard-pass counts   partials
__device__ float  g_w [NBH * 3 * SS * WW];    // window corrections (d, dx, dx^2)
__device__ float  g_wstd[WW];
__device__ float  g_msk[WW];

// ---------------------------------------------------------------------------
// Kernel A: per-64-row-chunk column sums. lane = column -> coalesced rows.
// ---------------------------------------------------------------------------
__global__ void __launch_bounds__(256) k_part(const float* __restrict__ preds) {
    int v = threadIdx.x >> 5, lane = threadIdx.x & 31;
    int col = blockIdx.x * 32 + lane;
    int gi = blockIdx.y * 8 + v;              // global 64-row chunk id
    const float* p = preds + (size_t)gi * 64 * WW + col;
    float s = 0.f;
#pragma unroll 8
    for (int r = 0; r < 64; r++) s += p[r * WW];
    g_p64[gi * WW + col] = s;
}

// ---------------------------------------------------------------------------
// Kernel B: main pass. Block (bw, bh): columns bw*32..+32, rows bh*512..+512.
// Each warp owns one 64-row chunk; lane = column. Single sweep: running cum
// from precomputed prefix, hard segment moments (double), sigmoid-window
// corrections near boundaries.
// ---------------------------------------------------------------------------
__global__ void __launch_bounds__(256) k_main(const float* __restrict__ preds,
                                              const float* __restrict__ snakes) {
    __shared__ float  snk[SS][32];
    __shared__ double sA[NSEG][32];
    __shared__ double sC[NSEG][32];
    __shared__ float  sB[NSEG][32];
    __shared__ float  sw[3][SS][32];

    const int bw = blockIdx.x, bh = blockIdx.y;
    const int tid = threadIdx.x;
    const int v = tid >> 5, lane = tid & 31;
    const int col = bw * 32 + lane;

    for (int e = tid; e < SS * 32; e += 256)
        snk[e >> 5][e & 31] = snakes[(e >> 5) * WW + bw * 32 + (e & 31)];
    for (int e = tid; e < NSEG * 32; e += 256) {
        sA[e >> 5][e & 31] = 0.0; sC[e >> 5][e & 31] = 0.0; sB[e >> 5][e & 31] = 0.f;
    }
    for (int e = tid; e < 3 * SS * 32; e += 256)
        ((float*)sw)[e] = 0.f;
    __syncthreads();

    // chunk prefix + column total from g_p64
    const int gi = bh * 8 + v;
    float base = 0.f, mag = 0.f;
#pragma unroll
    for (int i = 0; i < NCH; i++) {
        float p = g_p64[i * WW + col];
        if (i < gi) base += p;
        mag += p;
    }
    const float inv = 1.0f / mag;

    const int h0 = gi * 64;
    const float* p = preds + (size_t)h0 * WW + col;

    // init hard-segment index: j = #{b : s_b <= h0}
    int j = 0;
    while (j < SS && snk[j][lane] <= (float)h0) j++;
    float sNext = (j < SS) ? snk[j][lane] : 3.0e38f;
    int wLo = 0, wHi = 0;

    float cum = base;
    double aD = 0.0, cD = 0.0;
    float bF = 0.f;

#pragma unroll 4
    for (int r = 0; r < 64; r++) {
        const float hf = (float)(h0 + r);
        cum += p[(size_t)r * WW];
        const float x = cum * inv;

        if (hf >= sNext) {                    // crossed boundary: flush + advance
            atomicAdd(&sA[j][lane], aD);
            atomicAdd(&sC[j][lane], cD);
            atomicAdd(&sB[j][lane], bF);
            aD = cD = 0.0; bF = 0.f;
            j++;
            while (j < SS && snk[j][lane] <= hf) j++;
            sNext = (j < SS) ? snk[j][lane] : 3.0e38f;
        }
        double dx = (double)x;
        aD += dx; cD += dx * dx; bF += 1.f;

        // active window range: boundaries with |s_b - h| <= WIN
        while (wLo < SS && snk[wLo][lane] < hf - WIN) wLo++;
        while (wHi < SS && snk[wHi][lane] <= hf + WIN) wHi++;
        for (int b = wLo; b < wHi; b++) {
            float t = snk[b][lane] - hf;
            float u = __expf(-fabsf(t));
            float sg = u / (1.f + u);
            float dlt = (t > 0.f) ? -sg : sg;   // sigmoid - step, stable both sides
            atomicAdd(&sw[0][b][lane], dlt);
            atomicAdd(&sw[1][b][lane], dlt * x);
            atomicAdd(&sw[2][b][lane], dlt * x * x);
        }
    }
    atomicAdd(&sA[j][lane], aD);
    atomicAdd(&sC[j][lane], cD);
    atomicAdd(&sB[j][lane], bF);
    __syncthreads();

    // write per-(row-chunk-block) partials, laid out for coalesced reads in C
    for (int e = tid; e < NSEG * 32; e += 256) {
        int s = e >> 5, l = e & 31;
        int idx = (bh * NSEG + s) * WW + bw * 32 + l;
        g_hA[idx] = sA[s][l];
        g_hC[idx] = sC[s][l];
        g_hB[idx] = sB[s][l];
    }
    for (int e = tid; e < 3 * SS * 32; e += 256) {
        int k = e / (SS * 32), rem = e % (SS * 32);
        int b = rem >> 5, l = rem & 31;
        g_w[((bh * 3 + k) * SS + b) * WW + bw * 32 + l] = sw[k][b][l];
    }
}

// ---------------------------------------------------------------------------
// Kernel C: per-column combine -> wstd / mask
// ---------------------------------------------------------------------------
__global__ void __launch_bounds__(256) k_cols() {
    const int w = blockIdx.x * 256 + threadIdx.x;

    float mag = 0.f;
#pragma unroll
    for (int i = 0; i < NCH; i++) mag += g_p64[i * WW + w];

    float w0[SS], w1[SS], w2[SS];
#pragma unroll
    for (int b = 0; b < SS; b++) { w0[b] = 0.f; w1[b] = 0.f; w2[b] = 0.f; }
    for (int bh = 0; bh < NBH; bh++) {
#pragma unroll
        for (int b = 0; b < SS; b++) {
            w0[b] += g_w[((bh * 3 + 0) * SS + b) * WW + w];
            w1[b] += g_w[((bh * 3 + 1) * SS + b) * WW + w];
            w2[b] += g_w[((bh * 3 + 2) * SS + b) * WW + w];
        }
    }

    double wvar = 0.0;
#pragma unroll
    for (int s = 0; s < NSEG; s++) {
        double A = 0.0, C = 0.0;
        float Bf = 0.f;
        for (int bh = 0; bh < NBH; bh++) {
            int idx = (bh * NSEG + s) * WW + w;
            A += g_hA[idx]; C += g_hC[idx]; Bf += g_hB[idx];
        }
        double Bd = (double)Bf;
        if (s < SS) { Bd += (double)w0[s]; A += (double)w1[s]; C += (double)w2[s]; }
        if (s > 0)  { Bd -= (double)w0[s - 1]; A -= (double)w1[s - 1]; C -= (double)w2[s - 1]; }
        if (Bd > 1e-12) wvar += C - A * A / Bd;
    }

    bool m = (mag > 1.0f);
    g_wstd[w] = m ? (float)(wvar / (double)(NSEG * HH)) : 0.f;
    g_msk[w]  = m ? 1.f : 0.f;
}

// ---------------------------------------------------------------------------
// Kernel D: reduce 1024 columns -> scalar loss
// ---------------------------------------------------------------------------
__global__ void k_reduce(float* __restrict__ out) {
    int tid = threadIdx.x;
    float s = 0.f, c = 0.f;
    for (int i = tid; i < WW; i += 256) { s += g_wstd[i]; c += g_msk[i]; }
#pragma unroll
    for (int d = 16; d; d >>= 1) {
        s += __shfl_xor_sync(0xffffffffu, s, d);
        c += __shfl_xor_sync(0xffffffffu, c, d);
    }
    __shared__ float ws[8], wc[8];
    if ((tid & 31) == 0) { ws[tid >> 5] = s; wc[tid >> 5] = c; }
    __syncthreads();
    if (tid == 0) {
        float S_ = 0.f, C_ = 0.f;
#pragma unroll
        for (int k = 0; k < 8; k++) { S_ += ws[k]; C_ += wc[k]; }
        out[0] = S_ / C_;
    }
}

// ---------------------------------------------------------------------------
extern "C" void kernel_launch(void* const* d_in, const int* in_sizes, int n_in,
                              void* d_out, int out_size) {
    const float* snakes = (const float*)d_in[0];   // [16, 1024]
    const float* preds  = (const float*)d_in[1];   // [4096, 1024]
    (void)in_sizes; (void)n_in; (void)out_size;

    k_part<<<dim3(WW / 32, NBH), 256>>>(preds);
    k_main<<<dim3(WW / 32, NBH), 256>>>(preds, snakes);
    k_cols<<<WW / 256, 256>>>();
    k_reduce<<<1, 256>>>((float*)d_out);
}